// round 3
// baseline (speedup 1.0000x reference)
#include <cuda_runtime.h>
#include <math.h>

#define TT   1024
#define DMM  1024
#define HH   16
#define DD   64
#define RNK  32
#define NT   16          // TT / 64
#define NPAIR 136        // NT*(NT+1)/2 lower-triangular tile pairs
#define SCALE 0.125f     // D^-0.5

// ---------------- scratch (device globals; no allocations allowed) ----------
__device__ float g_q   [TT*DMM];
__device__ float g_k   [TT*DMM];
__device__ float g_v   [TT*DMM];
__device__ float g_wpre[TT*DMM];
__device__ float g_w   [TT*DMM];
__device__ float g_xw1 [TT*RNK];
__device__ float g_beta[TT*HH];
__device__ float g_M [HH*TT*TT];   // A = I + M (strict lower, beta-scaled w.w)
__device__ float g_Mk[HH*TT*TT];   // strict lower, beta-scaled w.k
__device__ float g_G [HH*TT*TT];   // Aqw -> G (in place, lower tiles only)
__device__ float g_S [HH*TT*TT];   // QK -> S -> P (in place)
__device__ float g_invA[HH*NT*64*64];
__device__ float g_o [TT*DMM];

// ---------------- 64x64 tile FMA core: acc(+/-)= As[i][k]*Bs[k][j] ----------
template<int PA, int PB, bool SUB>
__device__ __forceinline__ void mma64(const float As[][PA], const float Bs[][PB],
                                      float (&acc)[4][4], int ty, int tx)
{
#pragma unroll
    for (int kk = 0; kk < 64; kk++) {
        float a[4];
#pragma unroll
        for (int u = 0; u < 4; u++) a[u] = As[ty*4+u][kk];
        float4 bv = *(const float4*)&Bs[kk][tx*4];
        float b[4] = {bv.x, bv.y, bv.z, bv.w};
#pragma unroll
        for (int u = 0; u < 4; u++)
#pragma unroll
            for (int w2 = 0; w2 < 4; w2++)
                acc[u][w2] += (SUB ? -a[u]*b[w2] : a[u]*b[w2]);
    }
}

__device__ __forceinline__ void pair_map(int p, int& bi, int& bj)
{
    int b = 0;
    while ((b+1)*(b+2)/2 <= p) b++;
    bi = b; bj = p - b*(b+1)/2;
}

// ---------------- generic C[M,N] = A[M,K] @ B[K,N] --------------------------
// mode 0: plain, mode 1: 2*sigmoid epilogue (beta)
__global__ __launch_bounds__(256) void gemm64(
    const float* __restrict__ A, const float* __restrict__ B,
    float* __restrict__ C, int M, int N, int K, int mode)
{
    __shared__ float As[64][65];
    __shared__ __align__(16) float Bs[64][64];
    int tid = threadIdx.x, tx = tid & 15, ty = tid >> 4;
    int bm = blockIdx.y << 6, bn = blockIdx.x << 6;
    float acc[4][4] = {};
    for (int kt = 0; kt < K; kt += 64) {
        for (int l = tid; l < 4096; l += 256) {
            int r = l >> 6, c = l & 63;
            int gm = bm + r, gk = kt + c;
            As[r][c] = (gm < M && gk < K) ? A[(size_t)gm*K + gk] : 0.f;
        }
        for (int l = tid; l < 4096; l += 256) {
            int r = l >> 6, c = l & 63;
            int gk = kt + r, gn = bn + c;
            Bs[r][c] = (gk < K && gn < N) ? B[(size_t)gk*N + gn] : 0.f;
        }
        __syncthreads();
        mma64<65,64,false>(As, Bs, acc, ty, tx);
        __syncthreads();
    }
#pragma unroll
    for (int a = 0; a < 4; a++)
#pragma unroll
        for (int b = 0; b < 4; b++) {
            int r = bm + ty*4 + a, c = bn + tx*4 + b;
            if (r < M && c < N) {
                float v = acc[a][b];
                if (mode == 1) v = 2.f / (1.f + expf(-v));
                C[(size_t)r*N + c] = v;
            }
        }
}

// ---------------- causal depthwise conv(3) + SiLU + per-head L2 norm --------
__global__ void conv_norm_kernel(const float* __restrict__ conv_w)
{
    int t = blockIdx.x;
    int c = threadIdx.x;                       // 1024 threads = DM channels
    float x0  = g_wpre[t*DMM + c];
    float xm1 = (t >= 1) ? g_wpre[(t-1)*DMM + c] : 0.f;
    float xm2 = (t >= 2) ? g_wpre[(t-2)*DMM + c] : 0.f;
    float y = conv_w[c*3+0]*xm2 + conv_w[c*3+1]*xm1 + conv_w[c*3+2]*x0;
    y = y / (1.f + expf(-y));                  // SiLU
    float y2 = y * y;
#pragma unroll
    for (int o = 16; o; o >>= 1) y2 += __shfl_xor_sync(0xffffffffu, y2, o);
    __shared__ float wsum[32];
    if ((c & 31) == 0) wsum[c >> 5] = y2;
    __syncthreads();
    int h = c >> 6;
    float ss = wsum[2*h] + wsum[2*h+1];
    g_w[t*DMM + c] = y * rsqrtf(ss + 1e-6f);
}

// ---------------- per-head 64-dim dot products over lower tiles -------------
// C[h, r, c] = sum_d A[r, h*64+d] * B[c, h*64+d]
// mode 0/1: strict mask (r>c), row-scale beta[r,h]   (M / Mk)
// mode 2:   causal mask (c<=r)                        (Aqw)
// mode 3:   no mask                                   (QK)
__global__ __launch_bounds__(256) void headdot_kernel(
    const float* __restrict__ A, const float* __restrict__ B,
    float* __restrict__ C, int mode)
{
    int bi, bj; pair_map(blockIdx.x, bi, bj);
    int h = blockIdx.y;
    __shared__ float As[64][65];                   // [i][d]
    __shared__ __align__(16) float BsT[64][68];    // [d][j]  (68*4 bytes, 16B-aligned rows)
    int tid = threadIdx.x, tx = tid & 15, ty = tid >> 4;
    for (int l = tid; l < 4096; l += 256) {
        int r = l >> 6, c = l & 63;
        As[r][c] = A[(size_t)(bi*64 + r)*DMM + h*64 + c];
    }
    for (int l = tid; l < 4096; l += 256) {
        int r = l >> 6, c = l & 63;                // r=j, c=d
        BsT[c][r] = B[(size_t)(bj*64 + r)*DMM + h*64 + c];
    }
    __syncthreads();
    float acc[4][4] = {};
    mma64<65,68,false>(As, BsT, acc, ty, tx);
    size_t base = (size_t)h*TT*TT;
#pragma unroll
    for (int a = 0; a < 4; a++)
#pragma unroll
        for (int b = 0; b < 4; b++) {
            int r = bi*64 + ty*4 + a, c = bj*64 + tx*4 + b;
            float v = acc[a][b];
            if (mode <= 1)      v = (r > c)  ? g_beta[r*HH + h] * v : 0.f;
            else if (mode == 2) v = (c <= r) ? v : 0.f;
            C[base + (size_t)r*TT + c] = v;
        }
}

// ---------------- invert unit-lower diagonal blocks of A = I + M ------------
__global__ void inv_diag_kernel()
{
    int J = blockIdx.x, h = blockIdx.y;
    int c = threadIdx.x;                            // 64 threads, one per column
    __shared__ float L[64][65];
    __shared__ float X[64][65];
    const float* Mt = &g_M[(size_t)h*TT*TT + (size_t)(J*64)*TT + J*64];
    for (int r = 0; r < 64; r++) {
        L[r][c] = (r > c) ? Mt[(size_t)r*TT + c] : (r == c ? 1.f : 0.f);
        X[r][c] = (r == c) ? 1.f : 0.f;
    }
    __syncthreads();
    for (int r = 1; r < 64; r++) {
        if (c < r) {
            float a = 0.f;
            for (int s = c; s < r; s++) a += L[r][s] * X[s][c];
            X[r][c] = -a;
        }
        __syncthreads();
    }
    float* out = &g_invA[((size_t)h*NT + J)*4096];
    for (int r = 0; r < 64; r++) out[r*64 + c] = X[r][c];
}

// ---------------- blocked backward solve: G[:,J] = (Aqw[:,J]-Σ G[:,S]M[S,J])·invA_J
__global__ __launch_bounds__(256) void solve_step_kernel(int J)
{
    int I = J + blockIdx.x;
    int h = blockIdx.y;
    size_t base = (size_t)h*TT*TT;
    int tid = threadIdx.x, tx = tid & 15, ty = tid >> 4;
    __shared__ float Gs[64][65];
    __shared__ __align__(16) float Ms[64][64];

    float acc[4][4];
    const float* Aqw = &g_G[base + (size_t)(I*64)*TT + J*64];
#pragma unroll
    for (int a = 0; a < 4; a++) {
        float4 v = *(const float4*)&Aqw[(size_t)(ty*4+a)*TT + tx*4];
        acc[a][0] = v.x; acc[a][1] = v.y; acc[a][2] = v.z; acc[a][3] = v.w;
    }
    for (int S = J + 1; S <= I; S++) {
        const float* Gp = &g_G[base + (size_t)(I*64)*TT + S*64];
        const float* Mp = &g_M[base + (size_t)(S*64)*TT + J*64];
        __syncthreads();
        for (int l = tid; l < 4096; l += 256) { int r=l>>6,c=l&63; Gs[r][c] = Gp[(size_t)r*TT + c]; }
        for (int l = tid; l < 4096; l += 256) { int r=l>>6,c=l&63; Ms[r][c] = Mp[(size_t)r*TT + c]; }
        __syncthreads();
        mma64<65,64,true>(Gs, Ms, acc, ty, tx);
    }
    // multiply by invA_J: stage acc in Gs, invA in Ms
    __syncthreads();
#pragma unroll
    for (int a = 0; a < 4; a++)
#pragma unroll
        for (int b = 0; b < 4; b++) Gs[ty*4+a][tx*4+b] = acc[a][b];
    const float* Ip = &g_invA[((size_t)h*NT + J)*4096];
    for (int l = tid; l < 4096; l += 256) { int r=l>>6,c=l&63; Ms[r][c] = Ip[l]; }
    __syncthreads();
    float fin[4][4] = {};
    mma64<65,64,false>(Gs, Ms, fin, ty, tx);
    float* Gout = &g_G[base + (size_t)(I*64)*TT + J*64];
#pragma unroll
    for (int a = 0; a < 4; a++)
#pragma unroll
        for (int b = 0; b < 4; b++)
            Gout[(size_t)(ty*4+a)*TT + tx*4+b] = fin[a][b];
}

// ---------------- S = (QK - G @ Mk) * scale on lower tiles -------------------
__global__ __launch_bounds__(256) void s_kernel()
{
    int bi, bj; pair_map(blockIdx.x, bi, bj);
    int h = blockIdx.y;
    size_t base = (size_t)h*TT*TT;
    int tid = threadIdx.x, tx = tid & 15, ty = tid >> 4;
    __shared__ float Gs[64][65];
    __shared__ __align__(16) float Ms[64][64];
    float acc[4][4] = {};
    for (int S = bj; S <= bi; S++) {
        const float* Gp = &g_G [base + (size_t)(bi*64)*TT + S*64];
        const float* Mp = &g_Mk[base + (size_t)(S*64)*TT + bj*64];
        __syncthreads();
        for (int l = tid; l < 4096; l += 256) { int r=l>>6,c=l&63; Gs[r][c] = Gp[(size_t)r*TT + c]; }
        for (int l = tid; l < 4096; l += 256) { int r=l>>6,c=l&63; Ms[r][c] = Mp[(size_t)r*TT + c]; }
        __syncthreads();
        mma64<65,64,false>(Gs, Ms, acc, ty, tx);
    }
    float* Sp = &g_S[base + (size_t)(bi*64)*TT + bj*64];
#pragma unroll
    for (int a = 0; a < 4; a++)
#pragma unroll
        for (int b = 0; b < 4; b++) {
            size_t off = (size_t)(ty*4+a)*TT + tx*4+b;
            Sp[off] = (Sp[off] - acc[a][b]) * SCALE;
        }
}

// ---------------- causal row softmax (zero-fills to 64-tile boundary) -------
__global__ void softmax_kernel()
{
    int i = blockIdx.x, h = blockIdx.y;
    float* Sp = &g_S[(size_t)h*TT*TT + (size_t)i*TT];
    int n = i + 1;
    int tid = threadIdx.x;
    __shared__ float red1[8], red2[8];
    float m = -1e30f;
    for (int j = tid; j < n; j += 256) m = fmaxf(m, Sp[j]);
#pragma unroll
    for (int o = 16; o; o >>= 1) m = fmaxf(m, __shfl_xor_sync(0xffffffffu, m, o));
    if ((tid & 31) == 0) red1[tid >> 5] = m;
    __syncthreads();
    m = red1[0];
#pragma unroll
    for (int u = 1; u < 8; u++) m = fmaxf(m, red1[u]);
    float sum = 0.f;
    for (int j = tid; j < n; j += 256) sum += __expf(Sp[j] - m);
#pragma unroll
    for (int o = 16; o; o >>= 1) sum += __shfl_xor_sync(0xffffffffu, sum, o);
    if ((tid & 31) == 0) red2[tid >> 5] = sum;
    __syncthreads();
    sum = 0.f;
#pragma unroll
    for (int u = 0; u < 8; u++) sum += red2[u];
    float inv = 1.f / sum;
    int tile_end = ((i >> 6) + 1) << 6;
    for (int j = tid; j < tile_end; j += 256)
        Sp[j] = (j < n) ? __expf(Sp[j] - m) * inv : 0.f;
}

// ---------------- o = P @ V per head -----------------------------------------
__global__ __launch_bounds__(256) void pv_kernel()
{
    int I = blockIdx.x, h = blockIdx.y;
    size_t base = (size_t)h*TT*TT;
    int tid = threadIdx.x, tx = tid & 15, ty = tid >> 4;
    __shared__ float Ps[64][65];
    __shared__ __align__(16) float Vs[64][64];
    float acc[4][4] = {};
    for (int Jt = 0; Jt <= I; Jt++) {
        const float* Pp = &g_S[base + (size_t)(I*64)*TT + Jt*64];
        __syncthreads();
        for (int l = tid; l < 4096; l += 256) { int r=l>>6,c=l&63; Ps[r][c] = Pp[(size_t)r*TT + c]; }
        for (int l = tid; l < 4096; l += 256) { int r=l>>6,c=l&63; Vs[r][c] = g_v[(size_t)(Jt*64+r)*DMM + h*64 + c]; }
        __syncthreads();
        mma64<65,64,false>(Ps, Vs, acc, ty, tx);
    }
#pragma unroll
    for (int a = 0; a < 4; a++)
#pragma unroll
        for (int b = 0; b < 4; b++)
            g_o[(size_t)(I*64 + ty*4+a)*DMM + h*64 + tx*4+b] = acc[a][b];
}

// ---------------- launcher ----------------------------------------------------
extern "C" void kernel_launch(void* const* d_in, const int* in_sizes, int n_in,
                              void* d_out, int out_size)
{
    const float* x     = (const float*)d_in[0];
    const float* Wq    = (const float*)d_in[1];
    const float* Wk    = (const float*)d_in[2];
    const float* Wv    = (const float*)d_in[3];
    const float* Ww1   = (const float*)d_in[4];
    const float* Ww2   = (const float*)d_in[5];
    const float* convw = (const float*)d_in[6];
    const float* Wb    = (const float*)d_in[7];
    const float* Wo    = (const float*)d_in[8];

    float *q, *k, *v, *wpre, *w, *xw1, *beta, *Mp, *Mkp, *Gp, *Sp, *o;
    cudaGetSymbolAddress((void**)&q,    g_q);
    cudaGetSymbolAddress((void**)&k,    g_k);
    cudaGetSymbolAddress((void**)&v,    g_v);
    cudaGetSymbolAddress((void**)&wpre, g_wpre);
    cudaGetSymbolAddress((void**)&w,    g_w);
    cudaGetSymbolAddress((void**)&xw1,  g_xw1);
    cudaGetSymbolAddress((void**)&beta, g_beta);
    cudaGetSymbolAddress((void**)&Mp,   g_M);
    cudaGetSymbolAddress((void**)&Mkp,  g_Mk);
    cudaGetSymbolAddress((void**)&Gp,   g_G);
    cudaGetSymbolAddress((void**)&Sp,   g_S);
    cudaGetSymbolAddress((void**)&o,    g_o);

    dim3 blk(256);
    dim3 gFull(16, 16);

    // projections
    gemm64<<<gFull, blk>>>(x, Wq, q, TT, DMM, DMM, 0);
    gemm64<<<gFull, blk>>>(x, Wk, k, TT, DMM, DMM, 0);
    gemm64<<<gFull, blk>>>(x, Wv, v, TT, DMM, DMM, 0);
    gemm64<<<dim3(1, 16), blk>>>(x, Ww1, xw1, TT, RNK, DMM, 0);
    gemm64<<<dim3(1, 16), blk>>>(x, Wb, beta, TT, HH, DMM, 1);   // 2*sigmoid
    gemm64<<<gFull, blk>>>(xw1, Ww2, wpre, TT, DMM, RNK, 0);

    // conv + silu + per-head l2 norm
    conv_norm_kernel<<<TT, 1024>>>(convw);

    // per-head T x T products on lower tiles
    dim3 gPair(NPAIR, HH);
    headdot_kernel<<<gPair, blk>>>(w, w, Mp,  0);  // M  = strict beta w.w
    headdot_kernel<<<gPair, blk>>>(w, k, Mkp, 1);  // Mk = strict beta w.k
    headdot_kernel<<<gPair, blk>>>(q, w, Gp,  2);  // Aqw (causal) -> into g_G
    headdot_kernel<<<gPair, blk>>>(q, k, Sp,  3);  // QK -> into g_S

    // invert diagonal blocks of I + M, then blocked backward solve
    inv_diag_kernel<<<dim3(NT, HH), 64>>>();
    for (int J = NT - 1; J >= 0; J--)
        solve_step_kernel<<<dim3(NT - J, HH), blk>>>(J);

    // S = (QK - G Mk) * scale, softmax, P @ V
    s_kernel<<<gPair, blk>>>();
    softmax_kernel<<<dim3(TT, HH), blk>>>();
    pv_kernel<<<dim3(NT, HH), blk>>>();

    // output projection
    gemm64<<<gFull, blk>>>(o, Wo, (float*)d_out, TT, DMM, DMM, 0);
}

// round 4
// speedup vs baseline: 1.2909x; 1.2909x over previous
#include <cuda_runtime.h>
#include <math.h>
#include <stdint.h>

#define TT   1024
#define DMM  1024
#define HH   16
#define RNK  32
#define NT   16
#define NPAIR 136
#define SCALE 0.125f
#define NPROJ 3120     // 3*1024 + 32 + 16

// ---------------- scratch (device globals) ----------------------------------
__device__ float g_q   [TT*DMM];
__device__ float g_k   [TT*DMM];
__device__ float g_v   [TT*DMM];
__device__ float g_wpre[TT*DMM];
__device__ float g_w   [TT*DMM];
__device__ float g_xw1 [TT*RNK];
__device__ float g_beta[TT*HH];
__device__ float g_M [HH*TT*TT];
__device__ float g_Mk[HH*TT*TT];
__device__ float g_G [HH*TT*TT];
__device__ float g_S [HH*TT*TT];
__device__ float g_invA[HH*NT*64*64];
__device__ float g_o [TT*DMM];

// ---------------- tf32 helpers ----------------------------------------------
__device__ __forceinline__ float to_tf32(float x) {
    uint32_t u; asm("cvt.rna.tf32.f32 %0, %1;" : "=r"(u) : "f"(x));
    return __uint_as_float(u);
}

__device__ __forceinline__ void mma8(float (&c)[4], const uint32_t (&a)[4],
                                     const uint32_t (&b)[2]) {
    asm volatile(
        "mma.sync.aligned.m16n8k8.row.col.f32.tf32.tf32.f32 "
        "{%0,%1,%2,%3},{%4,%5,%6,%7},{%8,%9},{%0,%1,%2,%3};"
        : "+f"(c[0]), "+f"(c[1]), "+f"(c[2]), "+f"(c[3])
        : "r"(a[0]), "r"(a[1]), "r"(a[2]), "r"(a[3]), "r"(b[0]), "r"(b[1]));
}

// 64x64x64 tile MMA: As[m][k] (pad 68), Bs[k][n] (pad 73). 8 warps, warp tile 32x16.
__device__ __forceinline__ void mma_tile(const float (*As)[68], const float (*Bs)[73],
                                         float (&acc)[2][2][4],
                                         int wr, int wc, int g, int tig)
{
#pragma unroll
    for (int kb = 0; kb < 64; kb += 8) {
        uint32_t a[2][4], b[2][2];
#pragma unroll
        for (int mi = 0; mi < 2; mi++) {
            int r0 = wr + mi*16 + g;
            a[mi][0] = __float_as_uint(As[r0    ][kb + tig    ]);
            a[mi][1] = __float_as_uint(As[r0 + 8][kb + tig    ]);
            a[mi][2] = __float_as_uint(As[r0    ][kb + tig + 4]);
            a[mi][3] = __float_as_uint(As[r0 + 8][kb + tig + 4]);
        }
#pragma unroll
        for (int ni = 0; ni < 2; ni++) {
            int c0 = wc + ni*8 + g;
            b[ni][0] = __float_as_uint(Bs[kb + tig    ][c0]);
            b[ni][1] = __float_as_uint(Bs[kb + tig + 4][c0]);
        }
#pragma unroll
        for (int mi = 0; mi < 2; mi++)
#pragma unroll
            for (int ni = 0; ni < 2; ni++)
                mma8(acc[mi][ni], a[mi], b[ni]);
    }
}

__device__ __forceinline__ void pair_map(int p, int& bi, int& bj) {
    int b = 0;
    while ((b+1)*(b+2)/2 <= p) b++;
    bi = b; bj = p - b*(b+1)/2;
}

#define WARP_IDX                                   \
    int tid = threadIdx.x;                         \
    int lane = tid & 31, wid = tid >> 5;           \
    int wr = (wid >> 2) * 32, wc = (wid & 3) * 16; \
    int g = lane >> 2, tig = lane & 3;

// acc element -> (row,col) within 64x64 tile
#define ACC_ROW(mi,e) (wr + (mi)*16 + g + ((e)>>1)*8)
#define ACC_COL(ni,e) (wc + (ni)*8 + tig*2 + ((e)&1))

// ---------------- fused projection: x @ [Wq|Wk|Wv|Ww1|Wb] -------------------
__global__ __launch_bounds__(256) void proj_kernel(
    const float* __restrict__ x,  const float* __restrict__ Wq,
    const float* __restrict__ Wk, const float* __restrict__ Wv,
    const float* __restrict__ Ww1,const float* __restrict__ Wb)
{
    __shared__ float As[64][68];
    __shared__ float Bs[64][73];
    WARP_IDX;
    int bm = blockIdx.y * 64, bn = blockIdx.x * 64;
    float acc[2][2][4] = {};
    for (int kt = 0; kt < DMM; kt += 64) {
        __syncthreads();
        for (int l = tid; l < 4096; l += 256) {
            int r = l >> 6, c = l & 63;
            As[r][c] = to_tf32(x[(size_t)(bm + r)*DMM + kt + c]);
        }
        for (int l = tid; l < 4096; l += 256) {
            int r = l >> 6, c = l & 63;          // r: k-offset, c: n-offset
            int n = bn + c, kk = kt + r;
            float v = 0.f;
            if (n < 3072) {
                const float* W = (n < 1024) ? Wq : (n < 2048) ? Wk : Wv;
                v = W[(size_t)kk*DMM + (n & 1023)];
            } else if (n < 3104) v = Ww1[kk*RNK + (n - 3072)];
            else if (n < NPROJ)  v = Wb [kk*HH  + (n - 3104)];
            Bs[r][c] = to_tf32(v);
        }
        __syncthreads();
        mma_tile(As, Bs, acc, wr, wc, g, tig);
    }
#pragma unroll
    for (int mi = 0; mi < 2; mi++)
#pragma unroll
    for (int ni = 0; ni < 2; ni++)
#pragma unroll
    for (int e = 0; e < 4; e++) {
        int row = bm + ACC_ROW(mi, e);
        int col = bn + ACC_COL(ni, e);
        float v = acc[mi][ni][e];
        if      (col < 1024)  g_q[(size_t)row*DMM + col] = v;
        else if (col < 2048)  g_k[(size_t)row*DMM + (col - 1024)] = v;
        else if (col < 3072)  g_v[(size_t)row*DMM + (col - 2048)] = v;
        else if (col < 3104)  g_xw1[row*RNK + (col - 3072)] = v;
        else if (col < NPROJ) g_beta[row*HH + (col - 3104)] = 2.f/(1.f + expf(-v));
    }
}

// ---------------- generic C = A@B (M,N mult of 64; K arbitrary) -------------
__global__ __launch_bounds__(256) void gemm_tc(
    const float* __restrict__ A, const float* __restrict__ B,
    float* __restrict__ C, int N, int K)
{
    __shared__ float As[64][68];
    __shared__ float Bs[64][73];
    WARP_IDX;
    int bm = blockIdx.y * 64, bn = blockIdx.x * 64;
    float acc[2][2][4] = {};
    for (int kt = 0; kt < K; kt += 64) {
        __syncthreads();
        for (int l = tid; l < 4096; l += 256) {
            int r = l >> 6, c = l & 63;
            As[r][c] = (kt + c < K) ? to_tf32(A[(size_t)(bm + r)*K + kt + c]) : 0.f;
        }
        for (int l = tid; l < 4096; l += 256) {
            int r = l >> 6, c = l & 63;
            Bs[r][c] = (kt + r < K) ? to_tf32(B[(size_t)(kt + r)*N + bn + c]) : 0.f;
        }
        __syncthreads();
        mma_tile(As, Bs, acc, wr, wc, g, tig);
    }
#pragma unroll
    for (int mi = 0; mi < 2; mi++)
#pragma unroll
    for (int ni = 0; ni < 2; ni++)
#pragma unroll
    for (int e = 0; e < 4; e++)
        C[(size_t)(bm + ACC_ROW(mi, e))*N + bn + ACC_COL(ni, e)] = acc[mi][ni][e];
}

// ---------------- causal depthwise conv(3) + SiLU + per-head L2 norm --------
__global__ void conv_norm_kernel(const float* __restrict__ conv_w)
{
    int t = blockIdx.x;
    int c = threadIdx.x;
    float x0  = g_wpre[t*DMM + c];
    float xm1 = (t >= 1) ? g_wpre[(t-1)*DMM + c] : 0.f;
    float xm2 = (t >= 2) ? g_wpre[(t-2)*DMM + c] : 0.f;
    float y = conv_w[c*3+0]*xm2 + conv_w[c*3+1]*xm1 + conv_w[c*3+2]*x0;
    y = y / (1.f + expf(-y));
    float y2 = y * y;
#pragma unroll
    for (int o = 16; o; o >>= 1) y2 += __shfl_xor_sync(0xffffffffu, y2, o);
    __shared__ float wsum[32];
    if ((c & 31) == 0) wsum[c >> 5] = y2;
    __syncthreads();
    int h = c >> 6;
    float ss = wsum[2*h] + wsum[2*h+1];
    g_w[t*DMM + c] = y * rsqrtf(ss + 1e-6f);
}

// ---------------- per-head D=64 dot products on lower tiles ------------------
// mode 0/1: strict (r>c), *beta[r,h]; mode 2: causal; mode 3: none
__global__ __launch_bounds__(256) void headdot_kernel(
    const float* __restrict__ A, const float* __restrict__ B,
    float* __restrict__ C, int mode)
{
    int bi, bj; pair_map(blockIdx.x, bi, bj);
    int h = blockIdx.y;
    __shared__ float As[64][68];   // [i][d]
    __shared__ float Bs[64][73];   // [d][j]
    WARP_IDX;
    for (int l = tid; l < 4096; l += 256) {
        int r = l >> 6, c = l & 63;
        As[r][c] = to_tf32(A[(size_t)(bi*64 + r)*DMM + h*64 + c]);
    }
    for (int l = tid; l < 4096; l += 256) {
        int r = l >> 6, c = l & 63;            // r=j, c=d
        Bs[c][r] = to_tf32(B[(size_t)(bj*64 + r)*DMM + h*64 + c]);
    }
    __syncthreads();
    float acc[2][2][4] = {};
    mma_tile(As, Bs, acc, wr, wc, g, tig);
    size_t base = (size_t)h*TT*TT;
#pragma unroll
    for (int mi = 0; mi < 2; mi++)
#pragma unroll
    for (int ni = 0; ni < 2; ni++)
#pragma unroll
    for (int e = 0; e < 4; e++) {
        int r = bi*64 + ACC_ROW(mi, e), c = bj*64 + ACC_COL(ni, e);
        float v = acc[mi][ni][e];
        if (mode <= 1)      v = (r > c)  ? g_beta[r*HH + h] * v : 0.f;
        else if (mode == 2) v = (c <= r) ? v : 0.f;
        C[base + (size_t)r*TT + c] = v;
    }
}

// ---------------- invert unit-lower diagonal blocks of A = I + M -------------
__global__ void inv_diag_kernel()
{
    int J = blockIdx.x, h = blockIdx.y;
    int c = threadIdx.x;
    __shared__ float L[64][65];
    __shared__ float X[64][65];
    const float* Mt = &g_M[(size_t)h*TT*TT + (size_t)(J*64)*TT + J*64];
    for (int r = 0; r < 64; r++) {
        L[r][c] = (r > c) ? Mt[(size_t)r*TT + c] : (r == c ? 1.f : 0.f);
        X[r][c] = (r == c) ? 1.f : 0.f;
    }
    __syncthreads();
    for (int r = 1; r < 64; r++) {
        if (c < r) {
            float a = 0.f;
            for (int s = c; s < r; s++) a += L[r][s] * X[s][c];
            X[r][c] = -a;
        }
        __syncthreads();
    }
    float* out = &g_invA[((size_t)h*NT + J)*4096];
    for (int r = 0; r < 64; r++) out[r*64 + c] = X[r][c];
}

// ---------------- blocked backward solve step ---------------------------------
__global__ __launch_bounds__(256) void solve_step_kernel(int J)
{
    int I = J + blockIdx.x;
    int h = blockIdx.y;
    size_t base = (size_t)h*TT*TT;
    __shared__ float Gs[64][68];
    __shared__ float Ms[64][73];
    WARP_IDX;
    float acc[2][2][4];
    const float* Aqw = &g_G[base + (size_t)(I*64)*TT + J*64];
#pragma unroll
    for (int mi = 0; mi < 2; mi++)
#pragma unroll
    for (int ni = 0; ni < 2; ni++)
#pragma unroll
    for (int e = 0; e < 4; e++)
        acc[mi][ni][e] = Aqw[(size_t)ACC_ROW(mi,e)*TT + ACC_COL(ni,e)];

    for (int S = J + 1; S <= I; S++) {
        const float* Gp = &g_G[base + (size_t)(I*64)*TT + S*64];
        const float* Mp = &g_M[base + (size_t)(S*64)*TT + J*64];
        __syncthreads();
        for (int l = tid; l < 4096; l += 256) {
            int r = l >> 6, c = l & 63;
            Gs[r][c] = to_tf32(Gp[(size_t)r*TT + c]);
        }
        for (int l = tid; l < 4096; l += 256) {
            int r = l >> 6, c = l & 63;
            Ms[r][c] = to_tf32(-Mp[(size_t)r*TT + c]);   // negate: acc -= G*M
        }
        __syncthreads();
        mma_tile(Gs, Ms, acc, wr, wc, g, tig);
    }
    // multiply by invA_J
    __syncthreads();
#pragma unroll
    for (int mi = 0; mi < 2; mi++)
#pragma unroll
    for (int ni = 0; ni < 2; ni++)
#pragma unroll
    for (int e = 0; e < 4; e++)
        Gs[ACC_ROW(mi,e)][ACC_COL(ni,e)] = to_tf32(acc[mi][ni][e]);
    const float* Ip = &g_invA[((size_t)h*NT + J)*4096];
    for (int l = tid; l < 4096; l += 256) {
        int r = l >> 6, c = l & 63;
        Ms[r][c] = to_tf32(Ip[l]);
    }
    __syncthreads();
    float fin[2][2][4] = {};
    mma_tile(Gs, Ms, fin, wr, wc, g, tig);
    float* Gout = &g_G[base + (size_t)(I*64)*TT + J*64];
#pragma unroll
    for (int mi = 0; mi < 2; mi++)
#pragma unroll
    for (int ni = 0; ni < 2; ni++)
#pragma unroll
    for (int e = 0; e < 4; e++)
        Gout[(size_t)ACC_ROW(mi,e)*TT + ACC_COL(ni,e)] = fin[mi][ni][e];
}

// ---------------- S = (QK - G @ Mk) * scale -----------------------------------
__global__ __launch_bounds__(256) void s_kernel()
{
    int bi, bj; pair_map(blockIdx.x, bi, bj);
    int h = blockIdx.y;
    size_t base = (size_t)h*TT*TT;
    __shared__ float Gs[64][68];
    __shared__ float Ms[64][73];
    WARP_IDX;
    float acc[2][2][4] = {};
    for (int S = bj; S <= bi; S++) {
        const float* Gp = &g_G [base + (size_t)(bi*64)*TT + S*64];
        const float* Mp = &g_Mk[base + (size_t)(S*64)*TT + bj*64];
        __syncthreads();
        for (int l = tid; l < 4096; l += 256) {
            int r = l >> 6, c = l & 63;
            Gs[r][c] = to_tf32(Gp[(size_t)r*TT + c]);
        }
        for (int l = tid; l < 4096; l += 256) {
            int r = l >> 6, c = l & 63;
            Ms[r][c] = to_tf32(Mp[(size_t)r*TT + c]);
        }
        __syncthreads();
        mma_tile(Gs, Ms, acc, wr, wc, g, tig);
    }
    float* Sp = &g_S[base + (size_t)(bi*64)*TT + bj*64];
#pragma unroll
    for (int mi = 0; mi < 2; mi++)
#pragma unroll
    for (int ni = 0; ni < 2; ni++)
#pragma unroll
    for (int e = 0; e < 4; e++) {
        size_t off = (size_t)ACC_ROW(mi,e)*TT + ACC_COL(ni,e);
        Sp[off] = (Sp[off] - acc[mi][ni][e]) * SCALE;
    }
}

// ---------------- causal row softmax ------------------------------------------
__global__ void softmax_kernel()
{
    int i = blockIdx.x, h = blockIdx.y;
    float* Sp = &g_S[(size_t)h*TT*TT + (size_t)i*TT];
    int n = i + 1;
    int tid = threadIdx.x;
    __shared__ float red1[8], red2[8];
    float m = -1e30f;
    for (int j = tid; j < n; j += 256) m = fmaxf(m, Sp[j]);
#pragma unroll
    for (int o = 16; o; o >>= 1) m = fmaxf(m, __shfl_xor_sync(0xffffffffu, m, o));
    if ((tid & 31) == 0) red1[tid >> 5] = m;
    __syncthreads();
    m = red1[0];
#pragma unroll
    for (int u = 1; u < 8; u++) m = fmaxf(m, red1[u]);
    float sum = 0.f;
    for (int j = tid; j < n; j += 256) sum += __expf(Sp[j] - m);
#pragma unroll
    for (int o = 16; o; o >>= 1) sum += __shfl_xor_sync(0xffffffffu, sum, o);
    if ((tid & 31) == 0) red2[tid >> 5] = sum;
    __syncthreads();
    sum = 0.f;
#pragma unroll
    for (int u = 0; u < 8; u++) sum += red2[u];
    float inv = 1.f / sum;
    int tile_end = ((i >> 6) + 1) << 6;
    for (int j = tid; j < tile_end; j += 256)
        Sp[j] = (j < n) ? __expf(Sp[j] - m) * inv : 0.f;
}

// ---------------- o = P @ V per head -------------------------------------------
__global__ __launch_bounds__(256) void pv_kernel()
{
    int I = blockIdx.x, h = blockIdx.y;
    size_t base = (size_t)h*TT*TT;
    __shared__ float Ps[64][68];
    __shared__ float Vs[64][73];
    WARP_IDX;
    float acc[2][2][4] = {};
    for (int Jt = 0; Jt <= I; Jt++) {
        const float* Pp = &g_S[base + (size_t)(I*64)*TT + Jt*64];
        __syncthreads();
        for (int l = tid; l < 4096; l += 256) {
            int r = l >> 6, c = l & 63;
            Ps[r][c] = to_tf32(Pp[(size_t)r*TT + c]);
        }
        for (int l = tid; l < 4096; l += 256) {
            int r = l >> 6, c = l & 63;
            Vs[r][c] = to_tf32(g_v[(size_t)(Jt*64 + r)*DMM + h*64 + c]);
        }
        __syncthreads();
        mma_tile(Ps, Vs, acc, wr, wc, g, tig);
    }
#pragma unroll
    for (int mi = 0; mi < 2; mi++)
#pragma unroll
    for (int ni = 0; ni < 2; ni++)
#pragma unroll
    for (int e = 0; e < 4; e++)
        g_o[(size_t)(I*64 + ACC_ROW(mi,e))*DMM + h*64 + ACC_COL(ni,e)] = acc[mi][ni][e];
}

// ---------------- launcher ------------------------------------------------------
extern "C" void kernel_launch(void* const* d_in, const int* in_sizes, int n_in,
                              void* d_out, int out_size)
{
    const float* x     = (const float*)d_in[0];
    const float* Wq    = (const float*)d_in[1];
    const float* Wk    = (const float*)d_in[2];
    const float* Wv    = (const float*)d_in[3];
    const float* Ww1   = (const float*)d_in[4];
    const float* Ww2   = (const float*)d_in[5];
    const float* convw = (const float*)d_in[6];
    const float* Wb    = (const float*)d_in[7];
    const float* Wo    = (const float*)d_in[8];

    float *q, *k, *w, *wpre, *xw1, *Mp, *Mkp, *Gp, *Sp, *o;
    cudaGetSymbolAddress((void**)&q,    g_q);
    cudaGetSymbolAddress((void**)&k,    g_k);
    cudaGetSymbolAddress((void**)&w,    g_w);
    cudaGetSymbolAddress((void**)&wpre, g_wpre);
    cudaGetSymbolAddress((void**)&xw1,  g_xw1);
    cudaGetSymbolAddress((void**)&Mp,   g_M);
    cudaGetSymbolAddress((void**)&Mkp,  g_Mk);
    cudaGetSymbolAddress((void**)&Gp,   g_G);
    cudaGetSymbolAddress((void**)&Sp,   g_S);
    cudaGetSymbolAddress((void**)&o,    g_o);

    dim3 blk(256);

    // fused projections: q | k | v | xw1 | beta
    proj_kernel<<<dim3((NPROJ + 63)/64, 16), blk>>>(x, Wq, Wk, Wv, Ww1, Wb);

    // wpre = xw1 @ Ww2  (K=32)
    gemm_tc<<<dim3(16, 16), blk>>>(xw1, Ww2, wpre, DMM, RNK);

    // conv + silu + per-head l2 norm
    conv_norm_kernel<<<TT, 1024>>>(convw);

    // per-head T x T products on lower tiles
    dim3 gPair(NPAIR, HH);
    headdot_kernel<<<gPair, blk>>>(w, w, Mp,  0);   // M
    headdot_kernel<<<gPair, blk>>>(w, k, Mkp, 1);   // Mk
    headdot_kernel<<<gPair, blk>>>(q, w, Gp,  2);   // Aqw -> g_G
    headdot_kernel<<<gPair, blk>>>(q, k, Sp,  3);   // QK  -> g_S

    // triangular solve
    inv_diag_kernel<<<dim3(NT, HH), 64>>>();
    for (int J = NT - 1; J >= 0; J--)
        solve_step_kernel<<<dim3(NT - J, HH), blk>>>(J);

    // S = (QK - G Mk)*scale, softmax, P @ V
    s_kernel<<<gPair, blk>>>();
    softmax_kernel<<<dim3(TT, HH), blk>>>();
    pv_kernel<<<dim3(NT, HH), blk>>>();

    // output projection
    gemm_tc<<<dim3(16, 16), blk>>>(o, Wo, (float*)d_out, DMM, DMM);
}